// round 16
// baseline (speedup 1.0000x reference)
#include <cuda_runtime.h>
#include <cuda_fp16.h>
#include <cstdint>

#define BATCH 2
#define SEQ   8192
#define CDIM  1024
#define HDIM  64
#define NROWS (BATCH * SEQ)   // 16384
#define QKVW  (3 * HDIM)      // 192

// ---- device scratch (no allocations) --------------------------------------
__device__ __half g_wh[QKVW * CDIM];             // W^T fp16  [192][1024]

// ---- helpers ----------------------------------------------------------------
__device__ __forceinline__ uint32_t smem_u32(const void* p) {
    uint32_t a;
    asm("{ .reg .u64 t; cvta.to.shared.u64 t, %1; cvt.u32.u64 %0, t; }"
        : "=r"(a) : "l"(p));
    return a;
}
__device__ __forceinline__ void ldm_x4(uint32_t* r, uint32_t addr) {
    asm volatile("ldmatrix.sync.aligned.m8n8.x4.shared.b16 {%0,%1,%2,%3}, [%4];"
        : "=r"(r[0]), "=r"(r[1]), "=r"(r[2]), "=r"(r[3]) : "r"(addr));
}
// f16-accumulate MMA: c = 2x b32 regs (4 halfs)
__device__ __forceinline__ void mma_f16acc(uint32_t* c, const uint32_t* a, const uint32_t* b) {
    asm volatile("mma.sync.aligned.m16n8k16.row.col.f16.f16.f16.f16 "
        "{%0,%1}, {%2,%3,%4,%5}, {%6,%7}, {%0,%1};"
        : "+r"(c[0]), "+r"(c[1])
        : "r"(a[0]), "r"(a[1]), "r"(a[2]), "r"(a[3]), "r"(b[0]), "r"(b[1]));
}
#define CP_ASYNC16(sm, gm) \
    asm volatile("cp.async.cg.shared.global [%0], [%1], 16;" :: "r"(sm), "l"(gm) : "memory")
#define CP_COMMIT() asm volatile("cp.async.commit_group;" ::: "memory")
#define CP_WAIT0()  asm volatile("cp.async.wait_group 0;" ::: "memory")

__device__ __forceinline__ uint32_t pack_h2(float a, float b) {
    __half2 t = __floats2half2_rn(a, b);
    return *reinterpret_cast<uint32_t*>(&t);
}

// ---------------------------------------------------------------------------
// Pre-pass: W fp32 [1024][64] x3  ->  W^T fp16 [192][1024]
// ---------------------------------------------------------------------------
__global__ __launch_bounds__(512)
void conv_w(const float* __restrict__ Wq,
            const float* __restrict__ Wk,
            const float* __restrict__ Wv) {
    __shared__ float ts[32][65];
    const int mat = blockIdx.x >> 5;          // 0..2
    const int k0  = (blockIdx.x & 31) * 32;   // k tile
    const float* W = (mat == 0) ? Wq : ((mat == 1) ? Wk : Wv);
    const int tid = threadIdx.x;

    const int ln = tid & 63, lk = tid >> 6;   // 0..7
    #pragma unroll
    for (int i = 0; i < 4; i++)
        ts[lk + i * 8][ln] = W[(size_t)(k0 + lk + i * 8) * 64 + ln];
    __syncthreads();

    const int n = tid >> 3, kq = (tid & 7) * 4;
    __half* hd = g_wh + (size_t)(mat * 64 + n) * CDIM + k0 + kq;
    __half2 a = __floats2half2_rn(ts[kq + 0][n], ts[kq + 1][n]);
    __half2 b = __floats2half2_rn(ts[kq + 2][n], ts[kq + 3][n]);
    *reinterpret_cast<__half2*>(hd)     = a;
    *reinterpret_cast<__half2*>(hd + 2) = b;
}

// ---------------------------------------------------------------------------
// Fused QKV GEMM + windowed attention, f16-accumulate MMA + fp32 flush.
// 112 queries per CTA; A tile = 128 rows [m0-16, m0+112) clamped. N=192.
// BK=64 (16 chunks). 12 warps (384 thr): 2m x 6n, warp tile 64x32.
// f16 running acc flushed into fp32 masters every 2 k-steps (k=32 segments).
// ---------------------------------------------------------------------------
#define MTQ  112              // queries per CTA
#define MA   128              // A tile rows (16 halo + 112)
#define BK   64
#define NCH  (CDIM / BK)      // 16 chunks
#define NT   384              // threads
#define SA   72               // A/B smem row stride in halfs
#define OFF_A  0
#define OFF_B  (MA * SA * 2)                       // 18432
#define STAGE  (OFF_B + QKVW * SA * 2)             // 46080
// attention overlay (floats): qs[112*66] | ks[128*66] | vs[128*66]
#define ATT_FLOATS ((MTQ + MA + MA) * 66)          // 24288
#define FUSED_SMEM (ATT_FLOATS * 4 > 2 * STAGE ? ATT_FLOATS * 4 : 2 * STAGE)  // 97152

__global__ __launch_bounds__(NT, 1)
void qkv_attn(const float* __restrict__ x, float* __restrict__ out) {
    extern __shared__ char sm[];
    const uint32_t smb = smem_u32(sm);
    float* const sp = reinterpret_cast<float*>(sm);
    float* const qs = sp;                 // [112][66]
    float* const ks = sp + MTQ * 66;      // [128][66]
    float* const vs = ks + MA * 66;       // [128][66]

    const int tid  = threadIdx.x;
    const int wid  = tid >> 5;
    const int lane = tid & 31;
    const int wmm  = wid / 6;        // 0..1  (m-warp, 64 rows)
    const int wn   = wid % 6;        // 0..5  (n-warp, 32 cols)
    const int m0   = blockIdx.x * MTQ;

    float acc[4][4][4];               // fp32 masters
    #pragma unroll
    for (int mt = 0; mt < 4; mt++)
        #pragma unroll
        for (int nt = 0; nt < 4; nt++)
            #pragma unroll
            for (int q = 0; q < 4; q++) acc[mt][nt][q] = 0.f;

    uint32_t a16[4][4][2];            // f16 running accumulators
    #pragma unroll
    for (int mt = 0; mt < 4; mt++)
        #pragma unroll
        for (int nt = 0; nt < 4; nt++)
            { a16[mt][nt][0] = 0u; a16[mt][nt][1] = 0u; }

    const int a_row  = (lane & 15);
    const int a_col  = (lane >> 4) * 8;
    const int b_rowo = ((lane >> 4) << 3) + (lane & 7);
    const int b_col  = ((lane >> 3) & 1) * 8;

    // x loader: 128 rows x 16 float4 = 2048 -> <=6 per thread (guard)
    float4 xf[6];
    auto load_x = [&](int k0) {
        #pragma unroll
        for (int l = 0; l < 6; l++) {
            int idx = l * NT + tid;
            if (idx < MA * 16) {
                int row = idx >> 4, c4 = idx & 15;
                int gr = m0 - 16 + row;
                gr = gr < 0 ? 0 : (gr >= NROWS ? NROWS - 1 : gr);
                xf[l] = *reinterpret_cast<const float4*>(
                    x + (size_t)gr * CDIM + k0 + c4 * 4);
            }
        }
    };
    auto store_x = [&](char* stp) {
        #pragma unroll
        for (int l = 0; l < 6; l++) {
            int idx = l * NT + tid;
            if (idx < MA * 16) {
                int row = idx >> 4, c4 = idx & 15;
                uint2 hp = make_uint2(pack_h2(xf[l].x, xf[l].y), pack_h2(xf[l].z, xf[l].w));
                *reinterpret_cast<uint2*>(stp + OFF_A + (uint32_t)(row * SA + c4 * 4) * 2) = hp;
            }
        }
    };
    // B loader: 192 rows x 8 16B-units = 1536 -> 4 per thread
    auto issue_b = [&](uint32_t stn, int k0) {
        #pragma unroll
        for (int l = 0; l < 4; l++) {
            int idx = l * NT + tid;
            int n = idx >> 3, u = idx & 7;
            uint32_t so = (uint32_t)(n * SA) * 2 + u * 16;
            CP_ASYNC16(stn + OFF_B + so, g_wh + (size_t)n * CDIM + k0 + u * 8);
        }
        CP_COMMIT();
    };

    // flush f16 running acc into fp32 masters, zero f16 acc
    auto flush = [&]() {
        #pragma unroll
        for (int mt = 0; mt < 4; mt++)
            #pragma unroll
            for (int nt = 0; nt < 4; nt++) {
                __half2 h0 = *reinterpret_cast<__half2*>(&a16[mt][nt][0]);
                __half2 h1 = *reinterpret_cast<__half2*>(&a16[mt][nt][1]);
                float2 f0 = __half22float2(h0);
                float2 f1 = __half22float2(h1);
                acc[mt][nt][0] += f0.x; acc[mt][nt][1] += f0.y;
                acc[mt][nt][2] += f1.x; acc[mt][nt][3] += f1.y;
                a16[mt][nt][0] = 0u; a16[mt][nt][1] = 0u;
            }
    };

    // ---- prologue ----
    load_x(0);
    issue_b(smb, 0);
    store_x(sm);
    CP_WAIT0();
    __syncthreads();

    for (int c = 0; c < NCH; c++) {
        const int s = c & 1;
        const uint32_t st = smb + s * STAGE;
        const bool more = (c + 1 < NCH);

        if (more) {
            load_x((c + 1) * BK);
            issue_b(smb + (s ^ 1) * STAGE, (c + 1) * BK);
        }

        #pragma unroll
        for (int ksp = 0; ksp < 4; ksp++) {
            const int k0h = ksp * 16;
            uint32_t ah[4][4], bf[2][4];
            #pragma unroll
            for (int mt = 0; mt < 4; mt++) {
                uint32_t ao = (uint32_t)((wmm * 64 + mt * 16 + a_row) * SA + k0h + a_col) * 2;
                ldm_x4(ah[mt], st + OFF_A + ao);
            }
            #pragma unroll
            for (int g = 0; g < 2; g++) {
                uint32_t bo = (uint32_t)((wn * 32 + g * 16 + b_rowo) * SA + k0h + b_col) * 2;
                ldm_x4(bf[g], st + OFF_B + bo);
            }
            #pragma unroll
            for (int mt = 0; mt < 4; mt++)
                #pragma unroll
                for (int g = 0; g < 2; g++) {
                    mma_f16acc(a16[mt][2 * g],     ah[mt], &bf[g][0]);
                    mma_f16acc(a16[mt][2 * g + 1], ah[mt], &bf[g][2]);
                }
            if (ksp & 1) flush();    // every 2 k-steps (k=32)
        }

        if (more) {
            store_x(sm + (s ^ 1) * STAGE);
            CP_WAIT0();
            __syncthreads();
        }
    }

    // ---- scatter fragments into attention smem layout (scalar stores) ----
    __syncthreads();
    {
        const int grp = lane >> 2, tig = lane & 3;
        #pragma unroll
        for (int mt = 0; mt < 4; mt++) {
            #pragma unroll
            for (int nt = 0; nt < 4; nt++) {
                const int col = wn * 32 + nt * 8 + tig * 2;   // 0..191
                const int cm = col & 63;
                const int ho = (cm < 32) ? cm : cm + 1;       // padded half offset
                #pragma unroll
                for (int half = 0; half < 2; half++) {
                    const int row = wmm * 64 + mt * 16 + grp + half * 8;
                    float v0 = acc[mt][nt][half * 2];
                    float v1 = acc[mt][nt][half * 2 + 1];
                    if (col < 64) {
                        if (row >= 16) {
                            float* p = qs + (row - 16) * 66 + ho;
                            p[0] = v0; p[1] = v1;
                        }
                    } else if (col < 128) {
                        float* p = ks + row * 66 + ho;
                        p[0] = v0; p[1] = v1;
                    } else {
                        float* p = vs + row * 66 + ho;
                        p[0] = v0; p[1] = v1;
                    }
                }
            }
        }
    }
    __syncthreads();

    // ---- attention: warps 0..6, 16 queries x 2 dim-halves per warp ----
    if (wid < 7) {
        const int qi = wid * 16 + (lane & 15);     // 0..111
        const int h  = lane >> 4;
        const int d0 = h * 32;
        const int gq = m0 + qi;                    // global query row
        const int i  = gq & (SEQ - 1);             // batch-local position

        float q[32];
        {
            const float* qp = qs + qi * 66 + h * 33;
            #pragma unroll
            for (int cc = 0; cc < 32; cc++) q[cc] = qp[cc];
        }

        float sc[17];
        float mx = -1e30f;
        #pragma unroll
        for (int t = 0; t < 17; t++) {
            const float* kr = ks + (qi + t) * 66 + h * 33;
            float p0 = 0.f, p1 = 0.f, p2 = 0.f, p3 = 0.f;
            #pragma unroll
            for (int cc = 0; cc < 32; cc += 4) {
                p0 = fmaf(q[cc + 0], kr[cc + 0], p0);
                p1 = fmaf(q[cc + 1], kr[cc + 1], p1);
                p2 = fmaf(q[cc + 2], kr[cc + 2], p2);
                p3 = fmaf(q[cc + 3], kr[cc + 3], p3);
            }
            float p = (p0 + p1) + (p2 + p3);
            p += __shfl_xor_sync(0xffffffffu, p, 16);
            float d = (i - 16 + t >= 0) ? p * 0.125f : -1e30f;
            sc[t] = d;
            mx = fmaxf(mx, d);
        }

        float den = 0.f;
        #pragma unroll
        for (int t = 0; t < 17; t++) { sc[t] = __expf(sc[t] - mx); den += sc[t]; }
        const float inv = 1.0f / den;

        if (gq < NROWS) {
            float* op = out + (size_t)gq * HDIM + d0;
            #pragma unroll
            for (int cb = 0; cb < 32; cb += 4) {
                float a0 = 0.f, a1 = 0.f, a2 = 0.f, a3 = 0.f;
                #pragma unroll
                for (int t = 0; t < 17; t++) {
                    const float* vr = vs + (qi + t) * 66 + h * 33 + cb;
                    a0 = fmaf(sc[t], vr[0], a0);
                    a1 = fmaf(sc[t], vr[1], a1);
                    a2 = fmaf(sc[t], vr[2], a2);
                    a3 = fmaf(sc[t], vr[3], a3);
                }
                *reinterpret_cast<float4*>(op + cb) =
                    make_float4(a0 * inv, a1 * inv, a2 * inv, a3 * inv);
            }
        }
    }
}

// ---------------------------------------------------------------------------
extern "C" void kernel_launch(void* const* d_in, const int* in_sizes, int n_in,
                              void* d_out, int out_size)
{
    const float* x  = (const float*)d_in[0];
    const float* Wq = (const float*)d_in[1];
    const float* Wk = (const float*)d_in[2];
    const float* Wv = (const float*)d_in[3];
    float* out = (float*)d_out;

    cudaFuncSetAttribute(qkv_attn, cudaFuncAttributeMaxDynamicSharedMemorySize, FUSED_SMEM);

    const int grid = (NROWS + MTQ - 1) / MTQ;   // 147
    conv_w<<<96, 512>>>(Wq, Wk, Wv);
    qkv_attn<<<grid, NT, FUSED_SMEM>>>(x, out);
}

// round 17
// speedup vs baseline: 1.1556x; 1.1556x over previous
#include <cuda_runtime.h>
#include <cuda_fp16.h>
#include <cstdint>

#define BATCH 2
#define SEQ   8192
#define CDIM  1024
#define HDIM  64
#define NROWS (BATCH * SEQ)   // 16384
#define QKVW  (3 * HDIM)      // 192
#define GRIDN 147             // ceil(16384/112) -- all CTAs co-resident (1/SM)

// ---- device scratch (no allocations) --------------------------------------
__device__ __half g_wh[QKVW * CDIM];     // W^T fp16  [192][1024]
__device__ unsigned int g_bar;           // ticket barrier counter (zero-init)

// ---- helpers ----------------------------------------------------------------
__device__ __forceinline__ uint32_t smem_u32(const void* p) {
    uint32_t a;
    asm("{ .reg .u64 t; cvta.to.shared.u64 t, %1; cvt.u32.u64 %0, t; }"
        : "=r"(a) : "l"(p));
    return a;
}
__device__ __forceinline__ void ldm_x4(uint32_t* r, uint32_t addr) {
    asm volatile("ldmatrix.sync.aligned.m8n8.x4.shared.b16 {%0,%1,%2,%3}, [%4];"
        : "=r"(r[0]), "=r"(r[1]), "=r"(r[2]), "=r"(r[3]) : "r"(addr));
}
__device__ __forceinline__ void mma_f16(float* c, const uint32_t* a, const uint32_t* b) {
    asm volatile("mma.sync.aligned.m16n8k16.row.col.f32.f16.f16.f32 "
        "{%0,%1,%2,%3}, {%4,%5,%6,%7}, {%8,%9}, {%0,%1,%2,%3};"
        : "+f"(c[0]), "+f"(c[1]), "+f"(c[2]), "+f"(c[3])
        : "r"(a[0]), "r"(a[1]), "r"(a[2]), "r"(a[3]), "r"(b[0]), "r"(b[1]));
}
#define CP_ASYNC16(sm, gm) \
    asm volatile("cp.async.cg.shared.global [%0], [%1], 16;" :: "r"(sm), "l"(gm) : "memory")
#define CP_COMMIT() asm volatile("cp.async.commit_group;" ::: "memory")
#define CP_WAIT0()  asm volatile("cp.async.wait_group 0;" ::: "memory")

__device__ __forceinline__ uint32_t pack_h2(float a, float b) {
    __half2 t = __floats2half2_rn(a, b);
    return *reinterpret_cast<uint32_t*>(&t);
}

// ---------------------------------------------------------------------------
// Fused W-convert + QKV GEMM + windowed attention. Single kernel.
// 112 queries per CTA; A tile = 128 rows [m0-16, m0+112) clamped. N=192.
// BK=128 (8 chunks). 8 warps: 2m x 4n, warp tile 64x48. Halo-q skip.
// Prologue: each CTA converts 1/147 of W fp32->fp16 into g_wh, then a
// replay-safe ticket barrier gates the first B cp.async.
// ---------------------------------------------------------------------------
#define MTQ  112              // queries per CTA
#define MA   128              // A tile rows (16 halo + 112)
#define BK   128
#define NCH  (CDIM / BK)      // 8 chunks
#define NT   256              // threads
#define SA   136              // A/B smem row stride in halfs (272 B)
#define OFF_A  0
#define OFF_B  (MA * SA * 2)                       // 34816
#define STAGE  (OFF_B + QKVW * SA * 2)             // 87040
// attention overlay (floats): qs[112*66] | ks[128*66] | vs[128*66]
#define ATT_FLOATS ((MTQ + MA + MA) * 66)          // 24288
#define FUSED_SMEM (ATT_FLOATS * 4 > 2 * STAGE ? ATT_FLOATS * 4 : 2 * STAGE)  // 174080

__global__ __launch_bounds__(NT, 1)
void qkv_attn(const float* __restrict__ x,
              const float* __restrict__ Wq,
              const float* __restrict__ Wk,
              const float* __restrict__ Wv,
              float* __restrict__ out) {
    extern __shared__ char sm[];
    const uint32_t smb = smem_u32(sm);
    float* const sp = reinterpret_cast<float*>(sm);
    float* const qs = sp;                 // [112][66]
    float* const ks = sp + MTQ * 66;      // [128][66]
    float* const vs = ks + MA * 66;       // [128][66]

    __shared__ unsigned int s_tgt;

    const int tid  = threadIdx.x;
    const int wid  = tid >> 5;
    const int lane = tid & 31;
    const int wmm  = wid >> 2;       // 0..1  (m-warp, 64 rows)
    const int wn   = wid & 3;        // 0..3  (n-warp)
    const int m0   = blockIdx.x * MTQ;

    // B-tile physical column base per group: g0 = q, g1 = k, g2 = v
    const int colbase[3] = { wn * 16, 64 + wn * 16, 128 + wn * 16 };

    float acc[4][6][4];
    #pragma unroll
    for (int mt = 0; mt < 4; mt++)
        #pragma unroll
        for (int nt = 0; nt < 6; nt++)
            #pragma unroll
            for (int q = 0; q < 4; q++) acc[mt][nt][q] = 0.f;

    const int a_row  = (lane & 15);
    const int a_col  = (lane >> 4) * 8;
    const int b_rowo = ((lane >> 4) << 3) + (lane & 7);
    const int b_col  = ((lane >> 3) & 1) * 8;

    // x half-chunk loader: 128 rows x 64 k (16 float4/row) = 2048 -> 8/thread
    float4 xf[8];
    auto load_x = [&](int k0) {       // k0 = global k of this 64-wide half
        #pragma unroll
        for (int l = 0; l < 8; l++) {
            int idx = l * NT + tid;
            int row = idx >> 4, c4 = idx & 15;
            int gr = m0 - 16 + row;
            gr = gr < 0 ? 0 : (gr >= NROWS ? NROWS - 1 : gr);
            xf[l] = *reinterpret_cast<const float4*>(
                x + (size_t)gr * CDIM + k0 + c4 * 4);
        }
    };
    auto store_x = [&](char* stp, int half) {   // half: 0 -> k 0..63, 1 -> 64..127
        #pragma unroll
        for (int l = 0; l < 8; l++) {
            int idx = l * NT + tid;
            int row = idx >> 4, c4 = idx & 15;
            uint2 hp = make_uint2(pack_h2(xf[l].x, xf[l].y), pack_h2(xf[l].z, xf[l].w));
            *reinterpret_cast<uint2*>(
                stp + OFF_A + (uint32_t)(row * SA + half * 64 + c4 * 4) * 2) = hp;
        }
    };
    // B loader: 192 rows x 16 16B-units = 3072 -> 12 per thread
    auto issue_b = [&](uint32_t stn, int k0) {
        #pragma unroll
        for (int l = 0; l < 12; l++) {
            int idx = l * NT + tid;
            int n = idx >> 4, u = idx & 15;
            uint32_t so = (uint32_t)(n * SA) * 2 + u * 16;
            CP_ASYNC16(stn + OFF_B + so, g_wh + (size_t)n * CDIM + k0 + u * 8);
        }
        CP_COMMIT();
    };

    // one 4-kstep compute half (ksteps base..base+3)
    auto compute4 = [&](uint32_t st, int base) {
        #pragma unroll
        for (int ksp = 0; ksp < 4; ksp++) {
            const int k0h = (base + ksp) * 16;
            uint32_t ah[4][4], bf[3][4];
            #pragma unroll
            for (int mt = 0; mt < 4; mt++) {
                uint32_t ao = (uint32_t)((wmm * 64 + mt * 16 + a_row) * SA + k0h + a_col) * 2;
                ldm_x4(ah[mt], st + OFF_A + ao);
            }
            #pragma unroll
            for (int g = 0; g < 3; g++) {
                uint32_t bo = (uint32_t)((colbase[g] + b_rowo) * SA + k0h + b_col) * 2;
                ldm_x4(bf[g], st + OFF_B + bo);
            }
            #pragma unroll
            for (int mt = 0; mt < 4; mt++)
                #pragma unroll
                for (int g = 0; g < 3; g++) {
                    if (g == 0 && mt == 0) {
                        if (wmm != 0) {        // halo rows (wmm==0, mt==0) skip q
                            mma_f16(acc[0][0], ah[0], &bf[0][0]);
                            mma_f16(acc[0][1], ah[0], &bf[0][2]);
                        }
                    } else {
                        mma_f16(acc[mt][2 * g],     ah[mt], &bf[g][0]);
                        mma_f16(acc[mt][2 * g + 1], ah[mt], &bf[g][2]);
                    }
                }
        }
    };

    // ---- prologue: x LDG in flight, convert our W slice, ticket barrier ----
    load_x(0);

    // convert 1/147 of W: elements e = k*192 + n (read-coalesced over n)
    {
        const float* Wm[3] = { Wq, Wk, Wv };
        #pragma unroll
        for (int i = 0; i < 6; i++) {
            int e = (i * GRIDN + blockIdx.x) * NT + tid;
            if (e < QKVW * CDIM) {
                int k = e / QKVW;
                int n = e - k * QKVW;
                float v = Wm[n >> 6][(size_t)k * 64 + (n & 63)];
                g_wh[(size_t)n * CDIM + k] = __float2half_rn(v);
            }
        }
    }
    __threadfence();
    __syncthreads();
    if (tid == 0) {
        unsigned int t = atomicAdd(&g_bar, 1u);
        s_tgt = t - (t % GRIDN) + GRIDN;
    }

    store_x(sm, 0);        // overlaps other CTAs' convert/arrivals
    load_x(64);
    store_x(sm, 1);

    __syncthreads();       // s_tgt visible; smem stage-0 x stores done
    if (tid == 0) {
        volatile unsigned int* p = &g_bar;
        while (*p < s_tgt) { }
    }
    __threadfence();       // acquire: g_wh writes visible before cp.async reads
    __syncthreads();

    issue_b(smb, 0);
    CP_WAIT0();
    __syncthreads();

    for (int c = 0; c < NCH; c++) {
        const int s = c & 1;
        const uint32_t st = smb + s * STAGE;
        char* const stn_p = sm + (s ^ 1) * STAGE;
        const bool more = (c + 1 < NCH);

        if (more) {
            load_x((c + 1) * BK);                      // first half of next chunk
            issue_b(smb + (s ^ 1) * STAGE, (c + 1) * BK);
        }

        compute4(st, 0);                               // ksteps 0..3

        if (more) {
            store_x(stn_p, 0);
            load_x((c + 1) * BK + 64);                 // second half of next chunk
        }

        compute4(st, 4);                               // ksteps 4..7

        if (more) {
            store_x(stn_p, 1);
            CP_WAIT0();
            __syncthreads();
        }
    }

    // ---- scatter fragments into attention smem layout (scalar stores) ----
    __syncthreads();
    {
        const int grp = lane >> 2, tig = lane & 3;
        #pragma unroll
        for (int mt = 0; mt < 4; mt++) {
            #pragma unroll
            for (int g = 0; g < 3; g++) {
                #pragma unroll
                for (int j = 0; j < 2; j++) {
                    const int cm = wn * 16 + j * 8 + tig * 2;   // col within matrix
                    const int ho = (cm < 32) ? cm : cm + 1;      // padded half offset
                    #pragma unroll
                    for (int half = 0; half < 2; half++) {
                        const int row = wmm * 64 + mt * 16 + grp + half * 8;
                        float v0 = acc[mt][2 * g + j][half * 2];
                        float v1 = acc[mt][2 * g + j][half * 2 + 1];
                        if (g == 0) {
                            if (row >= 16) {
                                float* p = qs + (row - 16) * 66 + ho;
                                p[0] = v0; p[1] = v1;
                            }
                        } else if (g == 1) {
                            float* p = ks + row * 66 + ho;
                            p[0] = v0; p[1] = v1;
                        } else {
                            float* p = vs + row * 66 + ho;
                            p[0] = v0; p[1] = v1;
                        }
                    }
                }
            }
        }
    }
    __syncthreads();

    // ---- attention: warps 0..6, 16 queries x 2 dim-halves per warp ----
    if (wid < 7) {
        const int qi = wid * 16 + (lane & 15);     // 0..111
        const int h  = lane >> 4;
        const int d0 = h * 32;
        const int gq = m0 + qi;                    // global query row
        const int i  = gq & (SEQ - 1);             // batch-local position

        float q[32];
        {
            const float* qp = qs + qi * 66 + h * 33;
            #pragma unroll
            for (int cc = 0; cc < 32; cc++) q[cc] = qp[cc];
        }

        float sc[17];
        float mx = -1e30f;
        #pragma unroll
        for (int t = 0; t < 17; t++) {
            const float* kr = ks + (qi + t) * 66 + h * 33;
            float p0 = 0.f, p1 = 0.f, p2 = 0.f, p3 = 0.f;
            #pragma unroll
            for (int cc = 0; cc < 32; cc += 4) {
                p0 = fmaf(q[cc + 0], kr[cc + 0], p0);
                p1 = fmaf(q[cc + 1], kr[cc + 1], p1);
                p2 = fmaf(q[cc + 2], kr[cc + 2], p2);
                p3 = fmaf(q[cc + 3], kr[cc + 3], p3);
            }
            float p = (p0 + p1) + (p2 + p3);
            p += __shfl_xor_sync(0xffffffffu, p, 16);
            float d = (i - 16 + t >= 0) ? p * 0.125f : -1e30f;
            sc[t] = d;
            mx = fmaxf(mx, d);
        }

        float den = 0.f;
        #pragma unroll
        for (int t = 0; t < 17; t++) { sc[t] = __expf(sc[t] - mx); den += sc[t]; }
        const float inv = 1.0f / den;

        if (gq < NROWS) {
            float* op = out + (size_t)gq * HDIM + d0;
            #pragma unroll
            for (int cb = 0; cb < 32; cb += 4) {
                float a0 = 0.f, a1 = 0.f, a2 = 0.f, a3 = 0.f;
                #pragma unroll
                for (int t = 0; t < 17; t++) {
                    const float* vr = vs + (qi + t) * 66 + h * 33 + cb;
                    a0 = fmaf(sc[t], vr[0], a0);
                    a1 = fmaf(sc[t], vr[1], a1);
                    a2 = fmaf(sc[t], vr[2], a2);
                    a3 = fmaf(sc[t], vr[3], a3);
                }
                *reinterpret_cast<float4*>(op + cb) =
                    make_float4(a0 * inv, a1 * inv, a2 * inv, a3 * inv);
            }
        }
    }
}

// ---------------------------------------------------------------------------
extern "C" void kernel_launch(void* const* d_in, const int* in_sizes, int n_in,
                              void* d_out, int out_size)
{
    const float* x  = (const float*)d_in[0];
    const float* Wq = (const float*)d_in[1];
    const float* Wk = (const float*)d_in[2];
    const float* Wv = (const float*)d_in[3];
    float* out = (float*)d_out;

    cudaFuncSetAttribute(qkv_attn, cudaFuncAttributeMaxDynamicSharedMemorySize, FUSED_SMEM);

    qkv_attn<<<GRIDN, NT, FUSED_SMEM>>>(x, Wq, Wk, Wv, out);
}